// round 1
// baseline (speedup 1.0000x reference)
#include <cuda_runtime.h>

// HermitePolynomialMatrixND: out[w,0,a,p] = norm_p[p] * exp(-0.5*|x_wa|^2)
//                                         * H_{q0(p)}(x0) H_{q1(p)}(x1) H_{q2(p)}(x2)
// W=131072 walkers, A=16 particles, D=3, P=16 orbitals, max Hermite order 3.
// Pure HBM-bound: 24 MB read + 128 MB write.

#define NWALKERS 131072
#define APART    16
#define PORB     16
#define NPAIRS   (NWALKERS * APART)          // 2,097,152
#define NTHREADS (NPAIRS * 4)                // 4 threads per pair, 4 orbitals each

// Multi-index table (product(range(18),repeat=3) stable-sorted by sum, first 16):
// p : (q0,q1,q2)
// 0:(0,0,0) 1:(0,0,1) 2:(0,1,0) 3:(1,0,0)
// 4:(0,0,2) 5:(0,1,1) 6:(0,2,0) 7:(1,0,1)
// 8:(1,1,0) 9:(2,0,0) 10:(0,0,3) 11:(0,1,2)
// 12:(0,2,1) 13:(0,3,0) 14:(1,0,2) 15:(1,1,1)
__constant__ int cQ0[PORB] = {0,0,0,1, 0,0,0,1, 1,2,0,0, 0,0,1,1};
__constant__ int cQ1[PORB] = {0,0,1,0, 0,1,2,0, 1,0,0,1, 2,3,0,1};
__constant__ int cQ2[PORB] = {0,1,0,0, 2,1,0,1, 0,0,3,2, 1,0,2,1};

// Per-dimension normalization (2^n n! sqrt(pi))^{-1/2} for n=0..3
__constant__ float cN[4] = {
    0.7511255444649425f,   // pi^{-1/4}
    0.5311259660135984f,   // pi^{-1/4} / sqrt(2)
    0.2655629830067992f,   // pi^{-1/4} / sqrt(8)
    0.1084156300841463f    // pi^{-1/4} / sqrt(48)
};

__device__ __forceinline__ float hsel(int q, float h0, float h1, float h2, float h3) {
    // Predicated select chain — no divergence, no local-memory arrays.
    float r = h0;
    r = (q == 1) ? h1 : r;
    r = (q == 2) ? h2 : r;
    r = (q == 3) ? h3 : r;
    return r;
}

__global__ void __launch_bounds__(256)
hermite_orbitals_kernel(const float* __restrict__ x, float4* __restrict__ out) {
    const int tid     = blockIdx.x * blockDim.x + threadIdx.x;   // 0 .. NTHREADS-1
    const int pair    = tid >> 2;                                // (w*A + a)
    const int quarter = tid & 3;                                 // which 4 orbitals

    // Load this pair's 3 coordinates (4 threads share them; L1 broadcast).
    const float* xp = x + pair * 3;
    const float x0 = __ldg(xp + 0);
    const float x1 = __ldg(xp + 1);
    const float x2 = __ldg(xp + 2);

    // Gaussian envelope
    const float env = __expf(-0.5f * (x0 * x0 + x1 * x1 + x2 * x2));

    // Physicists' Hermite up to order 3 per dim:
    // H0=1, H1=2x, H2=2x*H1-2, H3=2x*H2-4*H1
    const float t0 = 2.0f * x0, t1 = 2.0f * x1, t2 = 2.0f * x2;
    const float a1 = t0;
    const float a2 = t0 * a1 - 2.0f;
    const float a3 = t0 * a2 - 4.0f * a1;
    const float b1 = t1;
    const float b2 = t1 * b1 - 2.0f;
    const float b3 = t1 * b2 - 4.0f * b1;
    const float c1 = t2;
    const float c2 = t2 * c1 - 2.0f;
    const float c3 = t2 * c2 - 4.0f * c1;

    const int pbase = quarter << 2;
    float v[4];
#pragma unroll
    for (int i = 0; i < 4; i++) {
        const int p  = pbase + i;
        const int q0 = cQ0[p];
        const int q1 = cQ1[p];
        const int q2 = cQ2[p];
        float val = cN[q0] * cN[q1] * cN[q2] * env;
        val *= hsel(q0, 1.0f, a1, a2, a3);
        val *= hsel(q1, 1.0f, b1, b2, b3);
        val *= hsel(q2, 1.0f, c1, c2, c3);
        v[i] = val;
    }

    // Output float4 #tid: 8 consecutive threads cover two full 128B lines.
    out[tid] = make_float4(v[0], v[1], v[2], v[3]);
}

extern "C" void kernel_launch(void* const* d_in, const int* in_sizes, int n_in,
                              void* d_out, int out_size) {
    (void)in_sizes; (void)n_in; (void)out_size;
    const float* x = (const float*)d_in[0];
    float4* out = (float4*)d_out;
    constexpr int threads = 256;
    constexpr int blocks  = NTHREADS / threads;   // 32768
    hermite_orbitals_kernel<<<blocks, threads>>>(x, out);
}

// round 2
// speedup vs baseline: 2.8663x; 2.8663x over previous
#include <cuda_runtime.h>

// HermitePolynomialMatrixND on GB300.
// out[w,0,a,p] = norm_p[p] * exp(-0.5*|x_wa|^2) * H_{q0}(x0) H_{q1}(x1) H_{q2}(x2)
// W=131072, A=16, D=3, P=16, max Hermite order 3.
//
// R2 design: one thread per (w,a) pair; all multi-index / normalization data
// constant-folded into immediates (no LDC, no select chains); 4x STG.128
// streaming stores per thread.

#define NWALKERS 131072
#define APART    16
#define NPAIRS   (NWALKERS * APART)   // 2,097,152 threads

__global__ void __launch_bounds__(256)
hermite_orbitals_kernel(const float* __restrict__ x, float4* __restrict__ out) {
    const int pair = blockIdx.x * blockDim.x + threadIdx.x;   // w*16 + a

    // --- load coordinates (warp reads 384B contiguous; L2-resident across replays)
    const float* xp = x + pair * 3;
    const float x0 = __ldg(xp + 0);
    const float x1 = __ldg(xp + 1);
    const float x2 = __ldg(xp + 2);

    // --- Gaussian envelope
    const float e = __expf(-0.5f * (x0 * x0 + x1 * x1 + x2 * x2));

    // --- physicists' Hermite, orders 1..3 per dim:
    // H1 = 2x, H2 = 2x*H1 - 2, H3 = 2x*H2 - 4*H1
    const float t0 = 2.0f * x0, t1 = 2.0f * x1, t2 = 2.0f * x2;
    const float a1 = t0, a2 = t0 * a1 - 2.0f, a3 = t0 * a2 - 4.0f * a1;
    const float b1 = t1, b2 = t1 * b1 - 2.0f, b3 = t1 * b2 - 4.0f * b1;
    const float c1 = t2, c2 = t2 * c1 - 2.0f, c3 = t2 * c2 - 4.0f * c1;

    // --- per-dim norms (2^n n! sqrt(pi))^{-1/2}, folded into per-orbital products
    constexpr float N0 = 0.7511255444649425f;   // n=0
    constexpr float N1 = 0.5311259660135984f;   // n=1
    constexpr float N2 = 0.2655629830067992f;   // n=2
    constexpr float N3 = 0.1084156300841463f;   // n=3

    constexpr float P000 = N0 * N0 * N0;
    constexpr float P001 = N0 * N0 * N1;
    constexpr float P002 = N0 * N0 * N2;
    constexpr float P011 = N0 * N1 * N1;
    constexpr float P003 = N0 * N0 * N3;
    constexpr float P012 = N0 * N1 * N2;
    constexpr float P111 = N1 * N1 * N1;

    // shared envelope*norm subexpressions
    const float e000 = P000 * e;
    const float e001 = P001 * e;
    const float e002 = P002 * e;
    const float e011 = P011 * e;
    const float e003 = P003 * e;
    const float e012 = P012 * e;
    const float e111 = P111 * e;

    // multi-index order (first 16 of D=3 tuples stable-sorted by sum):
    //  0:(0,0,0)  1:(0,0,1)  2:(0,1,0)  3:(1,0,0)
    //  4:(0,0,2)  5:(0,1,1)  6:(0,2,0)  7:(1,0,1)
    //  8:(1,1,0)  9:(2,0,0) 10:(0,0,3) 11:(0,1,2)
    // 12:(0,2,1) 13:(0,3,0) 14:(1,0,2) 15:(1,1,1)
    const float4 o0 = make_float4(e000,            e001 * c1,        e001 * b1,        e001 * a1);
    const float4 o1 = make_float4(e002 * c2,       e011 * b1 * c1,   e002 * b2,        e011 * a1 * c1);
    const float4 o2 = make_float4(e011 * a1 * b1,  e002 * a2,        e003 * c3,        e012 * b1 * c2);
    const float4 o3 = make_float4(e012 * b2 * c1,  e003 * b3,        e012 * a1 * c2,   e111 * a1 * b1 * c1);

    // --- 64B per pair, streaming (write-once; keep x L2-resident)
    float4* op = out + pair * 4;
    __stcs(op + 0, o0);
    __stcs(op + 1, o1);
    __stcs(op + 2, o2);
    __stcs(op + 3, o3);
}

extern "C" void kernel_launch(void* const* d_in, const int* in_sizes, int n_in,
                              void* d_out, int out_size) {
    (void)in_sizes; (void)n_in; (void)out_size;
    const float* x = (const float*)d_in[0];
    float4* out = (float4*)d_out;
    constexpr int threads = 256;
    constexpr int blocks  = NPAIRS / threads;   // 8192
    hermite_orbitals_kernel<<<blocks, threads>>>(x, out);
}

// round 3
// speedup vs baseline: 4.2666x; 1.4885x over previous
#include <cuda_runtime.h>

// HermitePolynomialMatrixND on GB300 — R3.
// out[w,0,a,p] = norm_p[p] * exp(-0.5*|x_wa|^2) * H_{q0}(x0) H_{q1}(x1) H_{q2}(x2)
// W=131072, A=16, D=3, P=16, max order 3.
//
// One thread per (w,a) pair, fully constant-folded orbitals (R2), plus a
// per-warp smem transpose so global stores are lane-contiguous STG.128
// (fixes the 64B-lane-stride wavefront inflation seen in R2's profile).

#define NWALKERS 131072
#define APART    16
#define NPAIRS   (NWALKERS * APART)   // 2,097,152 threads

__global__ void __launch_bounds__(256)
hermite_orbitals_kernel(const float* __restrict__ x, float4* __restrict__ out) {
    __shared__ float4 sm[256 * 4];                 // 16 KB: 4 float4 per thread

    const int tid  = threadIdx.x;
    const int lane = tid & 31;
    const int pair = blockIdx.x * 256 + tid;       // w*16 + a

    // --- load coordinates (warp reads 384B contiguous)
    const float* xp = x + pair * 3;
    const float x0 = __ldg(xp + 0);
    const float x1 = __ldg(xp + 1);
    const float x2 = __ldg(xp + 2);

    // --- Gaussian envelope
    const float e = __expf(-0.5f * (x0 * x0 + x1 * x1 + x2 * x2));

    // --- physicists' Hermite, orders 1..3 per dim
    const float t0 = 2.0f * x0, t1 = 2.0f * x1, t2 = 2.0f * x2;
    const float a1 = t0, a2 = t0 * a1 - 2.0f, a3 = t0 * a2 - 4.0f * a1;
    const float b1 = t1, b2 = t1 * b1 - 2.0f, b3 = t1 * b2 - 4.0f * b1;
    const float c1 = t2, c2 = t2 * c1 - 2.0f, c3 = t2 * c2 - 4.0f * c1;

    // --- per-dim norms (2^n n! sqrt(pi))^{-1/2}, folded to immediates
    constexpr float N0 = 0.7511255444649425f;
    constexpr float N1 = 0.5311259660135984f;
    constexpr float N2 = 0.2655629830067992f;
    constexpr float N3 = 0.1084156300841463f;
    constexpr float P000 = N0 * N0 * N0;
    constexpr float P001 = N0 * N0 * N1;
    constexpr float P002 = N0 * N0 * N2;
    constexpr float P011 = N0 * N1 * N1;
    constexpr float P003 = N0 * N0 * N3;
    constexpr float P012 = N0 * N1 * N2;
    constexpr float P111 = N1 * N1 * N1;

    const float e000 = P000 * e;
    const float e001 = P001 * e;
    const float e002 = P002 * e;
    const float e011 = P011 * e;
    const float e003 = P003 * e;
    const float e012 = P012 * e;
    const float e111 = P111 * e;

    // orbital table (first 16 D=3 multi-indices stable-sorted by total order)
    float4 o[4];
    o[0] = make_float4(e000,           e001 * c1,       e001 * b1,       e001 * a1);
    o[1] = make_float4(e002 * c2,      e011 * b1 * c1,  e002 * b2,       e011 * a1 * c1);
    o[2] = make_float4(e011 * a1 * b1, e002 * a2,       e003 * c3,       e012 * b1 * c2);
    o[3] = make_float4(e012 * b2 * c1, e003 * b3,       e012 * a1 * c2,  e111 * a1 * b1 * c1);

    // --- per-warp smem transpose (XOR swizzle, conflict-free both directions)
    float4* wsm = sm + (tid >> 5) * 128;           // this warp's 2048B region
    const int lq = lane & 3;
    const int lh = (lane >> 2) & 1;
#pragma unroll
    for (int j = 0; j < 4; j++)
        wsm[lane * 4 + (j ^ lq ^ lh)] = o[j];

    __syncwarp();

    // --- 4 coalesced STG.128: lane l writes float4 s*32+l of the warp region
    float4* wout = out + (size_t)(blockIdx.x * 256 + (tid & ~31)) * 4;
#pragma unroll
    for (int s = 0; s < 4; s++) {
        const int g = s * 32 + lane;               // float4 index in warp region
        const int p = g >> 2;                      // source pair (within warp)
        const int j = g & 3;                       // source slot
        const float4 v = wsm[p * 4 + (j ^ (p & 3) ^ ((p >> 2) & 1))];
        __stcs(wout + g, v);
    }
}

extern "C" void kernel_launch(void* const* d_in, const int* in_sizes, int n_in,
                              void* d_out, int out_size) {
    (void)in_sizes; (void)n_in; (void)out_size;
    const float* x = (const float*)d_in[0];
    float4* out = (float4*)d_out;
    constexpr int threads = 256;
    constexpr int blocks  = NPAIRS / threads;   // 8192
    hermite_orbitals_kernel<<<blocks, threads>>>(x, out);
}